// round 1
// baseline (speedup 1.0000x reference)
#include <cuda_runtime.h>

// Denoise_17669495455833: batched FISTA QP solve.
//   rows of 512 fp32, 2 passes x 100 iterations:
//     g     = 2(z - y) + 2*LAM * DtD(z)         (DtD = pentadiagonal [1 -4 6 -4 1] w/ boundary rows)
//     x_new = clip(z - step*g, 0, y)
//     t_new = 0.5*(1 + sqrt(1 + 4 t^2))
//     z_new = x_new + ((t-1)/t_new)*(x_new - x)
//   pass 2 re-solves with y = pass-1 output; final transpose in the ref is a no-op.
//
// Mapping: 1 warp per row, 16 elements per thread, all state in registers,
// +-2 stencil neighbors via 4 warp shuffles per iteration. No smem, no barriers,
// no global traffic inside the loop.

#define FULL_MASK 0xffffffffu

__global__ void __launch_bounds__(256)
denoise_fista_kernel(const float* __restrict__ in, float* __restrict__ out, int nrows)
{
    const int gw   = (int)((blockIdx.x * blockDim.x + threadIdx.x) >> 5);
    const int lane = (int)(threadIdx.x & 31);
    if (gw >= nrows) return;

    const float* rowp = in + (size_t)gw * 512 + lane * 16;

    float y[16], x[16], z[16];
    #pragma unroll
    for (int i = 0; i < 16; i += 4) {
        float4 v = *reinterpret_cast<const float4*>(rowp + i);
        y[i + 0] = v.x; y[i + 1] = v.y; y[i + 2] = v.z; y[i + 3] = v.w;
    }

    // LAM = 10, L = 2*(1 + 16*LAM), step = 1/L
    const float STEP = 1.0f / (2.0f * (1.0f + 16.0f * 10.0f));   // 1/322
    const float C_ZY = -2.0f * STEP;                              // coeff of (z - y)
    const float C_DT = -2.0f * 10.0f * STEP;                      // coeff of DtD(z)
    const bool first = (lane == 0);
    const bool last  = (lane == 31);

    #pragma unroll 1
    for (int pass = 0; pass < 2; ++pass) {
        #pragma unroll
        for (int k = 0; k < 16; ++k) { x[k] = y[k]; z[k] = y[k]; }   // x0 = proj(y) = y (y >= 0)
        float t = 1.0f;

        #pragma unroll 1
        for (int it = 0; it < 100; ++it) {
            // neighbor z values (previous iterate, warp-synchronous)
            float zm2 = __shfl_up_sync  (FULL_MASK, z[14], 1);  // z[base-2]
            float zm1 = __shfl_up_sync  (FULL_MASK, z[15], 1);  // z[base-1]
            float zp0 = __shfl_down_sync(FULL_MASK, z[0],  1);  // z[base+16]
            float zp1 = __shfl_down_sync(FULL_MASK, z[1],  1);  // z[base+17]

            // momentum scalar (uses old t in numerator, per reference)
            float t_new = 0.5f * (1.0f + sqrtf(fmaf(4.0f * t, t, 1.0f)));
            float coef  = (t - 1.0f) / t_new;
            t = t_new;

            float p2 = zm2, p1 = zm1;   // rotating window of OLD z[k-2], z[k-1]
            #pragma unroll
            for (int k = 0; k < 16; ++k) {
                float zc  = z[k];
                float zn1 = (k < 15) ? z[k + 1] : zp0;
                float zn2 = (k < 14) ? z[k + 2] : ((k == 14) ? zp0 : zp1);

                // interior row of DtD: z[j-2] - 4 z[j-1] + 6 z[j] - 4 z[j+1] + z[j+2]
                float a = fmaf(-4.0f, p1, p2);
                a = fmaf(6.0f, zc, a);
                a = fmaf(-4.0f, zn1, a);
                a += zn2;
                // boundary rows (j = 0, 1, n-2, n-1)
                if (first) {
                    if (k == 0) a = fmaf(-2.0f, zn1, zc) + zn2;                               //  z0 -2z1 + z2
                    if (k == 1) a = fmaf(-2.0f, p1, fmaf(5.0f, zc, fmaf(-4.0f, zn1, zn2)));   // -2z0 +5z1 -4z2 + z3
                }
                if (last) {
                    if (k == 14) a = fmaf(-4.0f, p1, p2) + fmaf(5.0f, zc, -2.0f * zn1);       // z[n-4] -4z[n-3] +5z[n-2] -2z[n-1]
                    if (k == 15) a = fmaf(-2.0f, p1, p2) + zc;                                // z[n-3] -2z[n-2] + z[n-1]
                }

                // x_new = clip(z - step*(2(z-y) + 2*LAM*a), 0, y)
                float v  = fmaf(C_ZY, zc - y[k], zc);
                v        = fmaf(C_DT, a, v);
                float xn = fminf(fmaxf(v, 0.0f), y[k]);

                // z_new = x_new + coef*(x_new - x)
                z[k] = fmaf(coef, xn - x[k], xn);
                x[k] = xn;

                p2 = p1; p1 = zc;
            }
        }

        if (pass == 0) {
            #pragma unroll
            for (int k = 0; k < 16; ++k) y[k] = x[k];   // pass 2 solves with y = pass-1 output
        }
    }

    float* orow = out + (size_t)gw * 512 + lane * 16;
    #pragma unroll
    for (int i = 0; i < 16; i += 4) {
        *reinterpret_cast<float4*>(orow + i) = make_float4(x[i], x[i + 1], x[i + 2], x[i + 3]);
    }
}

extern "C" void kernel_launch(void* const* d_in, const int* in_sizes, int n_in,
                              void* d_out, int out_size)
{
    const float* in  = (const float*)d_in[0];
    float*       out = (float*)d_out;
    const int nrows  = in_sizes[0] / 512;          // 32 * 512 = 16384 rows
    const int threads = 256;                        // 8 warps -> 8 rows per block
    const int blocks  = (nrows + 7) / 8;
    denoise_fista_kernel<<<blocks, threads>>>(in, out, nrows);
}

// round 2
// speedup vs baseline: 1.1268x; 1.1268x over previous
#include <cuda_runtime.h>

// Denoise_17669495455833: batched FISTA QP (2 passes x 100 iters, rows of 512 fp32).
// R2: issue-slot-bound per ncu (issue=90%). Use packed f32x2 FFMA2 by pairing TWO
// INDEPENDENT ROWS per warp: pair_j = (rowA[j], rowB[j]). Stencil/shuffles/boundary
// logic are identical for both halves -> no repacking. Clip is scalar FMNMX on pair
// halves. FISTA momentum coefficients precomputed once per launch by a setup kernel.

typedef unsigned long long u64;
#define FULL_MASK 0xffffffffu

__device__ u64 g_coefs[100];   // packed (coef, coef) per iteration

__device__ __forceinline__ u64 pk2(float lo, float hi) {
    u64 r;
    asm("mov.b64 %0, {%1,%2};" : "=l"(r) : "r"(__float_as_uint(lo)), "r"(__float_as_uint(hi)));
    return r;
}
__device__ __forceinline__ void upk2(u64 v, float& lo, float& hi) {
    unsigned a, b;
    asm("mov.b64 {%0,%1}, %2;" : "=r"(a), "=r"(b) : "l"(v));
    lo = __uint_as_float(a); hi = __uint_as_float(b);
}
__device__ __forceinline__ u64 fma2(u64 a, u64 b, u64 c) {
    u64 d;
    asm("fma.rn.f32x2 %0, %1, %2, %3;" : "=l"(d) : "l"(a), "l"(b), "l"(c));
    return d;
}
__device__ __forceinline__ u64 add2(u64 a, u64 b) {
    u64 d;
    asm("add.rn.f32x2 %0, %1, %2;" : "=l"(d) : "l"(a), "l"(b));
    return d;
}
__device__ __forceinline__ u64 rep2(float f) {
    unsigned u = __float_as_uint(f);
    return ((u64)u << 32) | (u64)u;
}

__global__ void coef_setup_kernel() {
    if (threadIdx.x == 0 && blockIdx.x == 0) {
        float t = 1.0f;
        for (int i = 0; i < 100; ++i) {
            float tn = 0.5f * (1.0f + sqrtf(fmaf(4.0f * t, t, 1.0f)));
            float c  = (t - 1.0f) / tn;
            unsigned u = __float_as_uint(c);
            g_coefs[i] = ((u64)u << 32) | (u64)u;
            t = tn;
        }
    }
}

__global__ void __launch_bounds__(128)
denoise_fista2_kernel(const float* __restrict__ in, float* __restrict__ out, int nrows)
{
    const int gw   = (int)((blockIdx.x * blockDim.x + threadIdx.x) >> 5);  // warp id = row pair id
    const int lane = (int)(threadIdx.x & 31);
    if (gw * 2 + 1 >= nrows) return;

    const float* rA = in + (size_t)(gw * 2)     * 512 + lane * 16;
    const float* rB = in + (size_t)(gw * 2 + 1) * 512 + lane * 16;

    u64 y[16], x[16], z[16];
    #pragma unroll
    for (int i = 0; i < 16; i += 4) {
        float4 a4 = *reinterpret_cast<const float4*>(rA + i);
        float4 b4 = *reinterpret_cast<const float4*>(rB + i);
        y[i + 0] = pk2(a4.x, b4.x);
        y[i + 1] = pk2(a4.y, b4.y);
        y[i + 2] = pk2(a4.z, b4.z);
        y[i + 3] = pk2(a4.w, b4.w);
    }

    // LAM = 10, step = 1/(2*(1+16*LAM)) = 1/322
    const float STEP = 1.0f / 322.0f;
    const u64 C_M4  = rep2(-4.0f);
    const u64 C_M2  = rep2(-2.0f);
    const u64 C_6   = rep2( 6.0f);
    const u64 C_5   = rep2( 5.0f);
    const u64 NEG1  = rep2(-1.0f);
    const u64 C_ZY  = rep2(-2.0f * STEP);           // coeff of (z - y)
    const u64 C_DT  = rep2(-2.0f * 10.0f * STEP);   // coeff of DtD(z)
    const bool first = (lane == 0);
    const bool last  = (lane == 31);

    #pragma unroll 1
    for (int pass = 0; pass < 2; ++pass) {
        #pragma unroll
        for (int k = 0; k < 16; ++k) { x[k] = y[k]; z[k] = y[k]; }   // x0 = proj(y) = y

        #pragma unroll 1
        for (int it = 0; it < 100; ++it) {
            // neighbor pairs (previous iterate, warp-synchronous)
            u64 zm2 = __shfl_up_sync  (FULL_MASK, z[14], 1);
            u64 zm1 = __shfl_up_sync  (FULL_MASK, z[15], 1);
            u64 zp0 = __shfl_down_sync(FULL_MASK, z[0],  1);
            u64 zp1 = __shfl_down_sync(FULL_MASK, z[1],  1);

            const u64 coefP = g_coefs[it];

            u64 p2 = zm2, p1 = zm1;   // rotating window of OLD z[k-2], z[k-1]
            #pragma unroll
            for (int k = 0; k < 16; ++k) {
                u64 zc  = z[k];
                u64 zn1 = (k < 15) ? z[k + 1] : zp0;
                u64 zn2 = (k < 14) ? z[k + 2] : ((k == 14) ? zp0 : zp1);

                // interior DtD row: z[j-2] - 4 z[j-1] + 6 z[j] - 4 z[j+1] + z[j+2]
                u64 a = fma2(p1, C_M4, p2);
                a = fma2(zc,  C_6,  a);
                a = fma2(zn1, C_M4, a);
                a = add2(a, zn2);
                // boundary rows (identical geometry for both packed rows)
                if (first) {
                    if (k == 0) {                       //  z0 - 2 z1 + z2
                        a = add2(fma2(zn1, C_M2, zc), zn2);
                    }
                    if (k == 1) {                       // -2 z0 + 5 z1 - 4 z2 + z3
                        a = fma2(zn1, C_M4, zn2);
                        a = fma2(zc,  C_5,  a);
                        a = fma2(p1,  C_M2, a);
                    }
                }
                if (last) {
                    if (k == 14) {                      // z[n-4] - 4 z[n-3] + 5 z[n-2] - 2 z[n-1]
                        a = fma2(p1,  C_M4, p2);
                        a = fma2(zc,  C_5,  a);
                        a = fma2(zn1, C_M2, a);
                    }
                    if (k == 15) {                      // z[n-3] - 2 z[n-2] + z[n-1]
                        a = add2(p2, zc);
                        a = fma2(p1, C_M2, a);
                    }
                }

                // v = z + C_ZY*(z - y) + C_DT*a
                u64 diff = fma2(y[k], NEG1, zc);        // z - y
                u64 v = fma2(diff, C_ZY, zc);
                v     = fma2(a,    C_DT, v);

                // x_new = clip(v, 0, y)  (scalar FMNMX on pair halves)
                float vlo, vhi, ylo, yhi;
                upk2(v, vlo, vhi);
                upk2(y[k], ylo, yhi);
                float xlo = fminf(fmaxf(vlo, 0.0f), ylo);
                float xhi = fminf(fmaxf(vhi, 0.0f), yhi);
                u64 xn = pk2(xlo, xhi);

                // z_new = x_new + coef*(x_new - x)
                u64 dx = fma2(x[k], NEG1, xn);
                z[k] = fma2(dx, coefP, xn);
                x[k] = xn;

                p2 = p1; p1 = zc;
            }
        }

        if (pass == 0) {
            #pragma unroll
            for (int k = 0; k < 16; ++k) y[k] = x[k];   // pass 2: y = pass-1 output
        }
    }

    float* oA = out + (size_t)(gw * 2)     * 512 + lane * 16;
    float* oB = out + (size_t)(gw * 2 + 1) * 512 + lane * 16;
    #pragma unroll
    for (int i = 0; i < 16; i += 4) {
        float4 a4, b4;
        upk2(x[i + 0], a4.x, b4.x);
        upk2(x[i + 1], a4.y, b4.y);
        upk2(x[i + 2], a4.z, b4.z);
        upk2(x[i + 3], a4.w, b4.w);
        *reinterpret_cast<float4*>(oA + i) = a4;
        *reinterpret_cast<float4*>(oB + i) = b4;
    }
}

extern "C" void kernel_launch(void* const* d_in, const int* in_sizes, int n_in,
                              void* d_out, int out_size)
{
    const float* in  = (const float*)d_in[0];
    float*       out = (float*)d_out;
    const int nrows  = in_sizes[0] / 512;            // 16384 rows
    coef_setup_kernel<<<1, 32>>>();
    const int warps  = nrows / 2;                    // 2 rows per warp
    const int blocks = (warps + 3) / 4;              // 4 warps per block
    denoise_fista2_kernel<<<blocks, 128>>>(in, out, nrows);
}

// round 3
// speedup vs baseline: 1.1289x; 1.0018x over previous
#include <cuda_runtime.h>

// Denoise_17669495455833: batched FISTA QP (2 passes x 100 iters, rows of 512 fp32).
// R2: issue-slot-bound per ncu (issue=90%). Use packed f32x2 FFMA2 by pairing TWO
// INDEPENDENT ROWS per warp: pair_j = (rowA[j], rowB[j]). Stencil/shuffles/boundary
// logic are identical for both halves -> no repacking. Clip is scalar FMNMX on pair
// halves. FISTA momentum coefficients precomputed once per launch by a setup kernel.

typedef unsigned long long u64;
#define FULL_MASK 0xffffffffu

__device__ u64 g_coefs[100];   // packed (coef, coef) per iteration

__device__ __forceinline__ u64 pk2(float lo, float hi) {
    u64 r;
    asm("mov.b64 %0, {%1,%2};" : "=l"(r) : "r"(__float_as_uint(lo)), "r"(__float_as_uint(hi)));
    return r;
}
__device__ __forceinline__ void upk2(u64 v, float& lo, float& hi) {
    unsigned a, b;
    asm("mov.b64 {%0,%1}, %2;" : "=r"(a), "=r"(b) : "l"(v));
    lo = __uint_as_float(a); hi = __uint_as_float(b);
}
__device__ __forceinline__ u64 fma2(u64 a, u64 b, u64 c) {
    u64 d;
    asm("fma.rn.f32x2 %0, %1, %2, %3;" : "=l"(d) : "l"(a), "l"(b), "l"(c));
    return d;
}
__device__ __forceinline__ u64 add2(u64 a, u64 b) {
    u64 d;
    asm("add.rn.f32x2 %0, %1, %2;" : "=l"(d) : "l"(a), "l"(b));
    return d;
}
__device__ __forceinline__ u64 rep2(float f) {
    unsigned u = __float_as_uint(f);
    return ((u64)u << 32) | (u64)u;
}

__global__ void coef_setup_kernel() {
    if (threadIdx.x == 0 && blockIdx.x == 0) {
        float t = 1.0f;
        for (int i = 0; i < 100; ++i) {
            float tn = 0.5f * (1.0f + sqrtf(fmaf(4.0f * t, t, 1.0f)));
            float c  = (t - 1.0f) / tn;
            unsigned u = __float_as_uint(c);
            g_coefs[i] = ((u64)u << 32) | (u64)u;
            t = tn;
        }
    }
}

__global__ void __launch_bounds__(128)
denoise_fista2_kernel(const float* __restrict__ in, float* __restrict__ out, int nrows)
{
    const int gw   = (int)((blockIdx.x * blockDim.x + threadIdx.x) >> 5);  // warp id = row pair id
    const int lane = (int)(threadIdx.x & 31);
    if (gw * 2 + 1 >= nrows) return;

    const float* rA = in + (size_t)(gw * 2)     * 512 + lane * 16;
    const float* rB = in + (size_t)(gw * 2 + 1) * 512 + lane * 16;

    u64 y[16], x[16], z[16];
    #pragma unroll
    for (int i = 0; i < 16; i += 4) {
        float4 a4 = *reinterpret_cast<const float4*>(rA + i);
        float4 b4 = *reinterpret_cast<const float4*>(rB + i);
        y[i + 0] = pk2(a4.x, b4.x);
        y[i + 1] = pk2(a4.y, b4.y);
        y[i + 2] = pk2(a4.z, b4.z);
        y[i + 3] = pk2(a4.w, b4.w);
    }

    // LAM = 10, step = 1/(2*(1+16*LAM)) = 1/322
    const float STEP = 1.0f / 322.0f;
    const u64 C_M4  = rep2(-4.0f);
    const u64 C_M2  = rep2(-2.0f);
    const u64 C_6   = rep2( 6.0f);
    const u64 C_5   = rep2( 5.0f);
    const u64 NEG1  = rep2(-1.0f);
    const u64 C_ZY  = rep2(-2.0f * STEP);           // coeff of (z - y)
    const u64 C_DT  = rep2(-2.0f * 10.0f * STEP);   // coeff of DtD(z)
    const bool first = (lane == 0);
    const bool last  = (lane == 31);

    #pragma unroll 1
    for (int pass = 0; pass < 2; ++pass) {
        #pragma unroll
        for (int k = 0; k < 16; ++k) { x[k] = y[k]; z[k] = y[k]; }   // x0 = proj(y) = y

        #pragma unroll 1
        for (int it = 0; it < 100; ++it) {
            // neighbor pairs (previous iterate, warp-synchronous)
            u64 zm2 = __shfl_up_sync  (FULL_MASK, z[14], 1);
            u64 zm1 = __shfl_up_sync  (FULL_MASK, z[15], 1);
            u64 zp0 = __shfl_down_sync(FULL_MASK, z[0],  1);
            u64 zp1 = __shfl_down_sync(FULL_MASK, z[1],  1);

            const u64 coefP = g_coefs[it];

            u64 p2 = zm2, p1 = zm1;   // rotating window of OLD z[k-2], z[k-1]
            #pragma unroll
            for (int k = 0; k < 16; ++k) {
                u64 zc  = z[k];
                u64 zn1 = (k < 15) ? z[k + 1] : zp0;
                u64 zn2 = (k < 14) ? z[k + 2] : ((k == 14) ? zp0 : zp1);

                // interior DtD row: z[j-2] - 4 z[j-1] + 6 z[j] - 4 z[j+1] + z[j+2]
                u64 a = fma2(p1, C_M4, p2);
                a = fma2(zc,  C_6,  a);
                a = fma2(zn1, C_M4, a);
                a = add2(a, zn2);
                // boundary rows (identical geometry for both packed rows)
                if (first) {
                    if (k == 0) {                       //  z0 - 2 z1 + z2
                        a = add2(fma2(zn1, C_M2, zc), zn2);
                    }
                    if (k == 1) {                       // -2 z0 + 5 z1 - 4 z2 + z3
                        a = fma2(zn1, C_M4, zn2);
                        a = fma2(zc,  C_5,  a);
                        a = fma2(p1,  C_M2, a);
                    }
                }
                if (last) {
                    if (k == 14) {                      // z[n-4] - 4 z[n-3] + 5 z[n-2] - 2 z[n-1]
                        a = fma2(p1,  C_M4, p2);
                        a = fma2(zc,  C_5,  a);
                        a = fma2(zn1, C_M2, a);
                    }
                    if (k == 15) {                      // z[n-3] - 2 z[n-2] + z[n-1]
                        a = add2(p2, zc);
                        a = fma2(p1, C_M2, a);
                    }
                }

                // v = z + C_ZY*(z - y) + C_DT*a
                u64 diff = fma2(y[k], NEG1, zc);        // z - y
                u64 v = fma2(diff, C_ZY, zc);
                v     = fma2(a,    C_DT, v);

                // x_new = clip(v, 0, y)  (scalar FMNMX on pair halves)
                float vlo, vhi, ylo, yhi;
                upk2(v, vlo, vhi);
                upk2(y[k], ylo, yhi);
                float xlo = fminf(fmaxf(vlo, 0.0f), ylo);
                float xhi = fminf(fmaxf(vhi, 0.0f), yhi);
                u64 xn = pk2(xlo, xhi);

                // z_new = x_new + coef*(x_new - x)
                u64 dx = fma2(x[k], NEG1, xn);
                z[k] = fma2(dx, coefP, xn);
                x[k] = xn;

                p2 = p1; p1 = zc;
            }
        }

        if (pass == 0) {
            #pragma unroll
            for (int k = 0; k < 16; ++k) y[k] = x[k];   // pass 2: y = pass-1 output
        }
    }

    float* oA = out + (size_t)(gw * 2)     * 512 + lane * 16;
    float* oB = out + (size_t)(gw * 2 + 1) * 512 + lane * 16;
    #pragma unroll
    for (int i = 0; i < 16; i += 4) {
        float4 a4, b4;
        upk2(x[i + 0], a4.x, b4.x);
        upk2(x[i + 1], a4.y, b4.y);
        upk2(x[i + 2], a4.z, b4.z);
        upk2(x[i + 3], a4.w, b4.w);
        *reinterpret_cast<float4*>(oA + i) = a4;
        *reinterpret_cast<float4*>(oB + i) = b4;
    }
}

extern "C" void kernel_launch(void* const* d_in, const int* in_sizes, int n_in,
                              void* d_out, int out_size)
{
    const float* in  = (const float*)d_in[0];
    float*       out = (float*)d_out;
    const int nrows  = in_sizes[0] / 512;            // 16384 rows
    coef_setup_kernel<<<1, 32>>>();
    const int warps  = nrows / 2;                    // 2 rows per warp
    const int blocks = (warps + 3) / 4;              // 4 warps per block
    denoise_fista2_kernel<<<blocks, 128>>>(in, out, nrows);
}